// round 9
// baseline (speedup 1.0000x reference)
#include <cuda_runtime.h>
#include <cuda_bf16.h>
#include <math.h>
#include <stdint.h>

// Problem constants
#define B_ 64
#define S_ 512
#define H_ 1024
#define K3 3072            // 3*H

// GEMM config
#define BN_ 64             // n-tile per CTA
#define KS 16              // K-split -> 16 x 16 = 256 CTAs
#define KC (K3 / KS)       // 192 K per CTA
#define NSTG (KC / 16)     // 12 k16 stages
#define ASTR 24            // smem A row stride in bf16 (48 B)
#define WSTR 24            // smem W row stride in bf16
#define GRID_ 256
#define NTHR 256

// dynamic smem layout (elements of bf16):
//   sWh: NSTG*BN_*WSTR = 18432   sWl: 18432
//   sAh: 2*64*ASTR     = 3072    sAl: 3072
#define SWELE (NSTG * BN_ * WSTR)
#define SAELE (2 * 64 * ASTR)
#define SMEM_BYTES ((2 * SWELE + 2 * SAELE) * 2)   // 86016 B

// Scratch (__device__ globals; no allocation allowed)
__device__ __align__(16) __nv_bfloat16 g_Ah[B_ * K3];
__device__ __align__(16) __nv_bfloat16 g_Al[B_ * K3];
__device__ __align__(16) float g_part[KS * B_ * H_];

// grid barrier state (generation counting; re-entrant across launches)
__device__ volatile unsigned g_gen = 0;
__device__ unsigned g_count = 0;

// ---------------------------------------------------------------------------
// helpers
// ---------------------------------------------------------------------------
__device__ __forceinline__ uint32_t smem_u32(const void* p) {
    return (uint32_t)__cvta_generic_to_shared(p);
}
__device__ __forceinline__ void ldmatrix_x4(uint32_t* r, uint32_t addr) {
    asm volatile("ldmatrix.sync.aligned.m8n8.x4.shared.b16 {%0,%1,%2,%3}, [%4];"
                 : "=r"(r[0]), "=r"(r[1]), "=r"(r[2]), "=r"(r[3]) : "r"(addr));
}
__device__ __forceinline__ void mma_bf16(float* c, const uint32_t* a,
                                         uint32_t b0, uint32_t b1) {
    asm volatile(
        "mma.sync.aligned.m16n8k16.row.col.f32.bf16.bf16.f32 "
        "{%0,%1,%2,%3}, {%4,%5,%6,%7}, {%8,%9}, {%0,%1,%2,%3};"
        : "+f"(c[0]), "+f"(c[1]), "+f"(c[2]), "+f"(c[3])
        : "r"(a[0]), "r"(a[1]), "r"(a[2]), "r"(a[3]), "r"(b0), "r"(b1));
}
__device__ __forceinline__ void split_bf16(float x, __nv_bfloat16& h, __nv_bfloat16& l) {
    h = __float2bfloat16_rn(x);
    l = __float2bfloat16_rn(x - __bfloat162float(h));
}
__device__ __forceinline__ void grid_barrier() {
    __syncthreads();
    if (threadIdx.x == 0) {
        __threadfence();                       // publish my global writes
        const unsigned g = g_gen;              // read before arriving
        if (atomicAdd(&g_count, 1u) == GRID_ - 1u) {
            g_count = 0;
            __threadfence();
            g_gen = g + 1;                     // release
        } else {
            while (g_gen == g) __nanosleep(64);
        }
        __threadfence();
    }
    __syncthreads();
}

// ---------------------------------------------------------------------------
// Fused persistent kernel: feats || W-convert  ->  MMA  ->  reduce
// grid 256 CTAs x 256 threads, all co-resident (launch_bounds(256,2)).
// ---------------------------------------------------------------------------
__global__ __launch_bounds__(NTHR, 2) void fused_kernel(
    const float* __restrict__ hs,
    const int* __restrict__ subj,
    const int* __restrict__ obj,
    const float* __restrict__ Wm,
    const float* __restrict__ bias,
    float* __restrict__ out)
{
    extern __shared__ __align__(16) char smem_raw[];
    __nv_bfloat16* sWh = (__nv_bfloat16*)smem_raw;
    __nv_bfloat16* sWl = sWh + SWELE;
    __nv_bfloat16* sAh = sWl + SWELE;
    __nv_bfloat16* sAl = sAh + SAELE;
    float4* red = (float4*)sAh;                 // phase-0 alias (sAh unused then)

    const int tid  = threadIdx.x;
    const int wid  = tid >> 5;
    const int lane = tid & 31;
    const int cta  = blockIdx.x;

    const int nb = cta & 15;                    // n-tile
    const int kb = cta >> 4;                    // k-chunk
    const int n0 = nb * BN_;
    const int k0 = kb * KC;

    // =======================================================================
    // Phase 0: warps 0-3 -> feats (3 tasks); warps 4-7 -> W tile to smem
    // =======================================================================
    if (tid < 128) {
        // ---- feats: tasks cta*3 + {0,1,2}; task = b*12 + seg*4 + hz ----
        const int h4l   = tid & 63;             // local float4 slot
        const int slice = tid >> 6;             // 0..1
        #pragma unroll 1
        for (int it = 0; it < 3; ++it) {
            const int task = cta * 3 + it;
            const int b   = task / 12;
            const int r   = task - b * 12;
            const int seg = r >> 2;
            const int hz  = r & 3;
            const int h4  = hz * 64 + h4l;

            const float4* base = (const float4*)(hs + (size_t)b * S_ * H_);
            float4 acc = make_float4(0.f, 0.f, 0.f, 0.f);
            float inv = 1.0f;

            if (seg == 0) {
                if (slice != 0) continue;
                acc = base[h4];
            } else {
                const int* rng = (seg == 1 ? subj : obj) + b * 2;
                const int s0 = rng[0];
                const int s1 = rng[1];
                const int cnt = s1 - s0;
                inv = 1.0f / (float)(cnt > 0 ? cnt : 1);

                const int sb = s0 + slice;
                #pragma unroll
                for (int i = 0; i < 16; ++i) {  // 2 slices x 16 -> len <= 32
                    const int s = sb + i * 2;
                    if (s < s1) {
                        const float4 v = base[(size_t)s * (H_ / 4) + h4];
                        acc.x += v.x; acc.y += v.y; acc.z += v.z; acc.w += v.w;
                    }
                }

                if (slice == 1) red[h4l] = acc;
                asm volatile("bar.sync 1, 128;" ::: "memory");
                if (slice != 0) continue;
                const float4 r1 = red[h4l];
                acc.x = (acc.x + r1.x) * inv;
                acc.y = (acc.y + r1.y) * inv;
                acc.z = (acc.z + r1.z) * inv;
                acc.w = (acc.w + r1.w) * inv;
            }

            __nv_bfloat16 h[4], l[4];
            split_bf16(acc.x, h[0], l[0]);
            split_bf16(acc.y, h[1], l[1]);
            split_bf16(acc.z, h[2], l[2]);
            split_bf16(acc.w, h[3], l[3]);
            const size_t off = (size_t)b * K3 + seg * H_ + (size_t)h4 * 4;
            *(__nv_bfloat162*)(g_Ah + off)     = __halves2bfloat162(h[0], h[1]);
            *(__nv_bfloat162*)(g_Ah + off + 2) = __halves2bfloat162(h[2], h[3]);
            *(__nv_bfloat162*)(g_Al + off)     = __halves2bfloat162(l[0], l[1]);
            *(__nv_bfloat162*)(g_Al + off + 2) = __halves2bfloat162(l[2], l[3]);
        }
    } else {
        // ---- W tile: 64 rows x 192 k fp32 -> bf16 hi/lo in smem ----
        // linear float4 index over [row 0..63][f4 0..47]; 24 per thread
        const int j = tid - 128;                // 0..127
        #pragma unroll 6
        for (int c = 0; c < 24; ++c) {
            const int idx = j + c * 128;        // 0..3071
            const int row = idx / 48;
            const int f4  = idx - row * 48;
            const int st  = f4 >> 2;
            const int k4  = f4 & 3;
            const float4 w = *(const float4*)(Wm + (size_t)(n0 + row) * K3 + k0 + f4 * 4);
            __nv_bfloat16 h0,h1,h2,h3,l0,l1,l2,l3;
            split_bf16(w.x, h0, l0); split_bf16(w.y, h1, l1);
            split_bf16(w.z, h2, l2); split_bf16(w.w, h3, l3);
            const int so = st * (BN_ * WSTR) + row * WSTR + k4 * 4;
            *(__nv_bfloat162*)(sWh + so)     = __halves2bfloat162(h0, h1);
            *(__nv_bfloat162*)(sWh + so + 2) = __halves2bfloat162(h2, h3);
            *(__nv_bfloat162*)(sWl + so)     = __halves2bfloat162(l0, l1);
            *(__nv_bfloat162*)(sWl + so + 2) = __halves2bfloat162(l2, l3);
        }
    }

    grid_barrier();     // feats published; W smem ordered by the syncthreads

    // =======================================================================
    // Phase 1: MMA mainloop.  A tiles global->smem (3-deep ring), W resident.
    // =======================================================================
    // A: threads 0-127 handle Ah, 128-255 handle Al; one uint4 (8 bf16) each
    const int ar = (tid & 127) >> 1;
    const int ap = tid & 1;
    const __nv_bfloat16* aQ =
        (tid < 128 ? g_Ah : g_Al) + (size_t)ar * K3 + k0 + ap * 8;
    __nv_bfloat16* aS = (tid < 128 ? sAh : sAl) + ar * ASTR + ap * 8;

    const int mw = wid & 1;                     // 2 m-warps
    const int nw = wid >> 1;                    // 4 n-warps
    const int a_row = (lane & 15);
    const int a_col = (lane >> 4) << 3;
    const int b_row = (lane & 7) | ((lane >> 4) << 3);
    const int b_col = ((lane >> 3) & 1) << 3;

    float acc[2][2][4];
    #pragma unroll
    for (int i = 0; i < 2; ++i)
        #pragma unroll
        for (int jj = 0; jj < 2; ++jj)
            #pragma unroll
            for (int c = 0; c < 4; ++c) acc[i][jj][c] = 0.f;

    uint4 q[3];
    q[0] = *(const uint4*)(aQ + 0 * 16);
    *(uint4*)(aS + 0 * (64 * ASTR)) = q[0];
    q[1] = *(const uint4*)(aQ + 1 * 16);
    q[2] = *(const uint4*)(aQ + 2 * 16);
    q[0] = *(const uint4*)(aQ + 3 * 16);
    __syncthreads();

    #pragma unroll
    for (int t = 0; t < NSTG; ++t) {
        const int cur = t & 1;

        uint32_t ahf[2][4], alf[2][4], whf[4], wlf[4];
        #pragma unroll
        for (int mi = 0; mi < 2; ++mi) {
            const int row = mw * 32 + mi * 16 + a_row;
            ldmatrix_x4(ahf[mi], smem_u32(sAh + cur * (64 * ASTR) + row * ASTR + a_col));
            ldmatrix_x4(alf[mi], smem_u32(sAl + cur * (64 * ASTR) + row * ASTR + a_col));
        }
        {
            const int row = nw * 16 + b_row;
            ldmatrix_x4(whf, smem_u32(sWh + t * (BN_ * WSTR) + row * WSTR + b_col));
            ldmatrix_x4(wlf, smem_u32(sWl + t * (BN_ * WSTR) + row * WSTR + b_col));
        }

        if (t + 1 < NSTG) {
            *(uint4*)(aS + (cur ^ 1) * (64 * ASTR)) = q[(t + 1) % 3];
            if (t + 4 < NSTG) q[(t + 1) % 3] = *(const uint4*)(aQ + (t + 4) * 16);
            __syncthreads();
        }

        #pragma unroll
        for (int mi = 0; mi < 2; ++mi)
            #pragma unroll
            for (int jj = 0; jj < 2; ++jj) {
                const int hf = jj * 2;
                mma_bf16(acc[mi][jj], ahf[mi], whf[hf], whf[hf + 1]); // ah*wh
                mma_bf16(acc[mi][jj], ahf[mi], wlf[hf], wlf[hf + 1]); // ah*wl
                mma_bf16(acc[mi][jj], alf[mi], whf[hf], whf[hf + 1]); // al*wh
            }
    }

    // write f32 partials
    {
        const int c_row = lane >> 2;
        const int c_col = (lane & 3) * 2;
        float* pbase = g_part + (size_t)kb * (B_ * H_);
        #pragma unroll
        for (int mi = 0; mi < 2; ++mi) {
            #pragma unroll
            for (int jj = 0; jj < 2; ++jj) {
                const int m = mw * 32 + mi * 16 + c_row;
                const int n = n0 + nw * 16 + jj * 8 + c_col;
                *(float2*)(pbase + (size_t)m * H_ + n) =
                    make_float2(acc[mi][jj][0], acc[mi][jj][1]);
                *(float2*)(pbase + (size_t)(m + 8) * H_ + n) =
                    make_float2(acc[mi][jj][2], acc[mi][jj][3]);
            }
        }
    }

    grid_barrier();

    // =======================================================================
    // Phase 2: reduce + bias + tanh.  One output element per thread.
    // =======================================================================
    {
        const int idx = cta * NTHR + tid;       // 0 .. 65535 = B_*H_
        const int n = idx & (H_ - 1);
        float s = bias[n];
        #pragma unroll
        for (int k = 0; k < KS; ++k)
            s += g_part[(size_t)k * (B_ * H_) + idx];
        out[idx] = tanhf(s);
    }
}

// ---------------------------------------------------------------------------
extern "C" void kernel_launch(void* const* d_in, const int* in_sizes, int n_in,
                              void* d_out, int out_size)
{
    const float* hs   = (const float*)d_in[0];   // (B, S, H) f32
    const int*   subj = (const int*)  d_in[1];   // (B, 2) i32
    const int*   obj  = (const int*)  d_in[2];   // (B, 2) i32
    const float* Wm   = (const float*)d_in[3];   // (H, 3H) f32
    const float* bias = (const float*)d_in[4];   // (H,) f32
    float*       out  = (float*)d_out;           // (B, H) f32

    (void)in_sizes; (void)n_in; (void)out_size;

    cudaFuncSetAttribute(fused_kernel,
                         cudaFuncAttributeMaxDynamicSharedMemorySize, SMEM_BYTES);
    fused_kernel<<<GRID_, NTHR, SMEM_BYTES>>>(hs, subj, obj, Wm, bias, out);
}

// round 11
// speedup vs baseline: 1.3265x; 1.3265x over previous
#include <cuda_runtime.h>
#include <cuda_bf16.h>
#include <math.h>
#include <stdint.h>

// Problem constants
#define B_ 64
#define S_ 512
#define H_ 1024
#define K3 3072            // 3*H

// GEMM config
#define BN_ 64             // n-tile per CTA
#define KS 16              // K-split -> grid (16, 16) = 256 CTAs
#define KC (K3 / KS)       // 192 K per CTA
#define NSTG (KC / 16)     // 12 k16 stages

// Scratch (__device__ globals; no allocation allowed)
__device__ __align__(16) __nv_bfloat16 g_Ah[B_ * K3];   // feats hi
__device__ __align__(16) __nv_bfloat16 g_Al[B_ * K3];   // feats lo
__device__ __align__(16) float g_part[KS * B_ * H_];    // 4 MB partials

// ---------------------------------------------------------------------------
// helpers
// ---------------------------------------------------------------------------
__device__ __forceinline__ uint32_t smem_u32(const void* p) {
    return (uint32_t)__cvta_generic_to_shared(p);
}
__device__ __forceinline__ void ldmatrix_x4(uint32_t* r, uint32_t addr) {
    asm volatile("ldmatrix.sync.aligned.m8n8.x4.shared.b16 {%0,%1,%2,%3}, [%4];"
                 : "=r"(r[0]), "=r"(r[1]), "=r"(r[2]), "=r"(r[3]) : "r"(addr));
}
__device__ __forceinline__ void mma_bf16(float* c, const uint32_t* a,
                                         uint32_t b0, uint32_t b1) {
    asm volatile(
        "mma.sync.aligned.m16n8k16.row.col.f32.bf16.bf16.f32 "
        "{%0,%1,%2,%3}, {%4,%5,%6,%7}, {%8,%9}, {%0,%1,%2,%3};"
        : "+f"(c[0]), "+f"(c[1]), "+f"(c[2]), "+f"(c[3])
        : "r"(a[0]), "r"(a[1]), "r"(a[2]), "r"(a[3]), "r"(b0), "r"(b1));
}
__device__ __forceinline__ void split_bf16(float x, __nv_bfloat16& h, __nv_bfloat16& l) {
    h = __float2bfloat16_rn(x);
    l = __float2bfloat16_rn(x - __bfloat162float(h));
}
// Split a float2 into packed bf16x2 hi and lo (lower half = .x, upper = .y).
// Numerically identical to split_bf16 per element (cvt.rn + exact residual).
__device__ __forceinline__ void cvt_split2(float2 v, uint32_t& h, uint32_t& l) {
    asm("cvt.rn.bf16x2.f32 %0, %1, %2;" : "=r"(h) : "f"(v.y), "f"(v.x));
    const float hy = __uint_as_float(h & 0xFFFF0000u);
    const float hx = __uint_as_float(h << 16);
    const float ly = v.y - hy;
    const float lx = v.x - hx;
    asm("cvt.rn.bf16x2.f32 %0, %1, %2;" : "=r"(l) : "f"(ly), "f"(lx));
}

// ---------------------------------------------------------------------------
// Kernel 1: feats -> bf16 hi/lo.  grid (B, 3, 4), 256 threads.
// z splits h 4-ways; 4 s-slices x 64 h4-slots; range length <= 32.
// ---------------------------------------------------------------------------
__global__ __launch_bounds__(256) void feats_kernel(
    const float* __restrict__ hs,
    const int* __restrict__ subj,
    const int* __restrict__ obj)
{
    __shared__ float4 red[3][64];

    const int b   = blockIdx.x;
    const int seg = blockIdx.y;
    const int hz  = blockIdx.z;
    const int tid = threadIdx.x;
    const int HC  = H_ / 4;

    const int h4    = hz * 64 + (tid & 63);
    const int slice = tid >> 6;              // 0..3

    const float4* base = (const float4*)(hs + (size_t)b * S_ * H_);

    float4 acc = make_float4(0.f, 0.f, 0.f, 0.f);
    float inv = 1.0f;

    if (seg == 0) {
        if (slice != 0) return;
        acc = base[h4];
    } else {
        const int* rng = (seg == 1 ? subj : obj) + b * 2;
        const int s0 = rng[0];
        const int s1 = rng[1];
        const int cnt = s1 - s0;
        inv = 1.0f / (float)(cnt > 0 ? cnt : 1);

        const int sb = s0 + slice;
        #pragma unroll
        for (int i = 0; i < 8; ++i) {        // 4 slices x 8 -> covers len 32
            const int s = sb + i * 4;
            if (s < s1) {
                const float4 v = base[(size_t)s * HC + h4];
                acc.x += v.x; acc.y += v.y; acc.z += v.z; acc.w += v.w;
            }
        }

        if (slice > 0) red[slice - 1][tid & 63] = acc;
        __syncthreads();
        if (slice != 0) return;
        const float4 r0 = red[0][tid & 63];
        const float4 r1 = red[1][tid & 63];
        const float4 r2 = red[2][tid & 63];
        acc.x += r0.x + r1.x + r2.x;
        acc.y += r0.y + r1.y + r2.y;
        acc.z += r0.z + r1.z + r2.z;
        acc.w += r0.w + r1.w + r2.w;
        acc.x *= inv; acc.y *= inv; acc.z *= inv; acc.w *= inv;
    }

    __nv_bfloat16 h[4], l[4];
    split_bf16(acc.x, h[0], l[0]);
    split_bf16(acc.y, h[1], l[1]);
    split_bf16(acc.z, h[2], l[2]);
    split_bf16(acc.w, h[3], l[3]);

    const size_t off = (size_t)b * K3 + seg * H_ + (size_t)h4 * 4;
    *(__nv_bfloat162*)(g_Ah + off)     = __halves2bfloat162(h[0], h[1]);
    *(__nv_bfloat162*)(g_Ah + off + 2) = __halves2bfloat162(h[2], h[3]);
    *(__nv_bfloat162*)(g_Al + off)     = __halves2bfloat162(l[0], l[1]);
    *(__nv_bfloat162*)(g_Al + off + 2) = __halves2bfloat162(l[2], l[3]);
}

// ---------------------------------------------------------------------------
// Kernel 2: split-bf16 3-term tensor-core GEMM partials.
// grid (16, 16) = 256 CTAs, 256 threads = 8 warps (2m x 4n), tile 64x64x192.
// A: ALL 12 stages resident in swizzled smem upfront -> no mainloop barriers.
// W: direct per-lane global fragment loads, f32->bf16 hi/lo split in regs.
// ---------------------------------------------------------------------------
__global__ __launch_bounds__(256, 2) void gemm_partial_kernel(
    const float* __restrict__ Wm)
{
    // [stage][row 0..63][2 chunks of 8 bf16], 32B rows, xor swizzle on chunk
    __shared__ __nv_bfloat16 sAh[NSTG * 64 * 16];   // 24 KB
    __shared__ __nv_bfloat16 sAl[NSTG * 64 * 16];   // 24 KB

    const int nb   = blockIdx.x;
    const int kb   = blockIdx.y;
    const int tid  = threadIdx.x;
    const int wid  = tid >> 5;
    const int lane = tid & 31;

    const int n0 = nb * BN_;
    const int k0 = kb * KC;

    // ---- load ALL A stages to smem (threads 0-127: hi, 128-255: lo) ----
    {
        const int ar = (tid & 127) >> 1;    // row 0..63
        const int ap = tid & 1;             // chunk 0/1
        const __nv_bfloat16* aQ =
            (tid < 128 ? g_Ah : g_Al) + (size_t)ar * K3 + k0 + ap * 8;
        __nv_bfloat16* aS = (tid < 128 ? sAh : sAl);
        const int slot = ap ^ ((ar >> 2) & 1);
        #pragma unroll
        for (int s = 0; s < NSTG; ++s)
            *(uint4*)(aS + s * 1024 + ar * 16 + slot * 8) =
                *(const uint4*)(aQ + s * 16);
    }
    __syncthreads();                         // ONLY barrier in this kernel

    // ---- warp layout: 2 m-warps x 4 n-warps; warp tile 32m x 16n ----
    const int mw = wid & 1;
    const int nw = wid >> 1;

    // A ldmatrix addressing (swizzled)
    const int a_row16 = lane & 15;
    const int a_chunk = lane >> 4;           // 0/1 -> k half

    // W fragment pointers: group g covers n = n0+nw*16+g*8+(lane>>2),
    // k = k0 + t*16 + (lane&3)*2 (+8 for b1)
    const float* wP0 = Wm + (size_t)(n0 + nw * 16 + (lane >> 2)) * K3
                          + k0 + (lane & 3) * 2;
    const float* wP1 = wP0 + (size_t)8 * K3;

    float acc[2][2][4];
    #pragma unroll
    for (int i = 0; i < 2; ++i)
        #pragma unroll
        for (int j = 0; j < 2; ++j)
            #pragma unroll
            for (int c = 0; c < 4; ++c) acc[i][j][c] = 0.f;

    // prefetch W stage 0
    float2 w00 = *(const float2*)(wP0 + 0);
    float2 w01 = *(const float2*)(wP0 + 8);
    float2 w10 = *(const float2*)(wP1 + 0);
    float2 w11 = *(const float2*)(wP1 + 8);

    #pragma unroll
    for (int t = 0; t < NSTG; ++t) {
        // prefetch next stage's W while we convert/compute this one
        float2 n00, n01, n10, n11;
        if (t + 1 < NSTG) {
            n00 = *(const float2*)(wP0 + (t + 1) * 16);
            n01 = *(const float2*)(wP0 + (t + 1) * 16 + 8);
            n10 = *(const float2*)(wP1 + (t + 1) * 16);
            n11 = *(const float2*)(wP1 + (t + 1) * 16 + 8);
        }

        // A fragments from smem
        uint32_t ahf[2][4], alf[2][4];
        #pragma unroll
        for (int mi = 0; mi < 2; ++mi) {
            const int row = mw * 32 + mi * 16 + a_row16;
            const int slot = a_chunk ^ ((row >> 2) & 1);
            const uint32_t off = t * 1024 + row * 16 + slot * 8;
            ldmatrix_x4(ahf[mi], smem_u32(sAh + off));
            ldmatrix_x4(alf[mi], smem_u32(sAl + off));
        }

        // W split -> packed bf16 fragments (b0,b1 per group, hi & lo)
        uint32_t b00h, b00l, b01h, b01l, b10h, b10l, b11h, b11l;
        cvt_split2(w00, b00h, b00l);   // group0 b0
        cvt_split2(w01, b01h, b01l);   // group0 b1
        cvt_split2(w10, b10h, b10l);   // group1 b0
        cvt_split2(w11, b11h, b11l);   // group1 b1

        #pragma unroll
        for (int mi = 0; mi < 2; ++mi) {
            mma_bf16(acc[mi][0], ahf[mi], b00h, b01h);  // ah*wh
            mma_bf16(acc[mi][0], ahf[mi], b00l, b01l);  // ah*wl
            mma_bf16(acc[mi][0], alf[mi], b00h, b01h);  // al*wh
            mma_bf16(acc[mi][1], ahf[mi], b10h, b11h);
            mma_bf16(acc[mi][1], ahf[mi], b10l, b11l);
            mma_bf16(acc[mi][1], alf[mi], b10h, b11h);
        }

        w00 = n00; w01 = n01; w10 = n10; w11 = n11;
    }

    // epilogue: f32 partials
    const int c_row = lane >> 2;
    const int c_col = (lane & 3) * 2;
    float* pbase = g_part + (size_t)kb * (B_ * H_);
    #pragma unroll
    for (int mi = 0; mi < 2; ++mi) {
        #pragma unroll
        for (int jj = 0; jj < 2; ++jj) {
            const int m = mw * 32 + mi * 16 + c_row;
            const int n = n0 + nw * 16 + jj * 8 + c_col;
            *(float2*)(pbase + (size_t)m * H_ + n) =
                make_float2(acc[mi][jj][0], acc[mi][jj][1]);
            *(float2*)(pbase + (size_t)(m + 8) * H_ + n) =
                make_float2(acc[mi][jj][2], acc[mi][jj][3]);
        }
    }
}

// ---------------------------------------------------------------------------
// Kernel 3: reduce K-split partials + bias + tanh (float4 vectorized)
// ---------------------------------------------------------------------------
__global__ __launch_bounds__(128) void reduce_kernel(
    const float* __restrict__ bias,
    float* __restrict__ out)
{
    const int idx4 = blockIdx.x * 128 + threadIdx.x;  // 0 .. B_*H_/4-1
    const int n4 = idx4 & (H_ / 4 - 1);

    const float4 bv = *(const float4*)(bias + n4 * 4);
    float4 s = bv;
    #pragma unroll
    for (int kb = 0; kb < KS; ++kb) {
        const float4 p = *(const float4*)(g_part + (size_t)kb * (B_ * H_) + idx4 * 4);
        s.x += p.x; s.y += p.y; s.z += p.z; s.w += p.w;
    }

    float4 o;
    o.x = tanhf(s.x); o.y = tanhf(s.y); o.z = tanhf(s.z); o.w = tanhf(s.w);
    *(float4*)(out + idx4 * 4) = o;
}

// ---------------------------------------------------------------------------
extern "C" void kernel_launch(void* const* d_in, const int* in_sizes, int n_in,
                              void* d_out, int out_size)
{
    const float* hs   = (const float*)d_in[0];   // (B, S, H) f32
    const int*   subj = (const int*)  d_in[1];   // (B, 2) i32
    const int*   obj  = (const int*)  d_in[2];   // (B, 2) i32
    const float* Wm   = (const float*)d_in[3];   // (H, 3H) f32
    const float* bias = (const float*)d_in[4];   // (H,) f32
    float*       out  = (float*)d_out;           // (B, H) f32

    (void)in_sizes; (void)n_in; (void)out_size;

    feats_kernel<<<dim3(B_, 3, 4), 256>>>(hs, subj, obj);
    gemm_partial_kernel<<<dim3(H_ / BN_, KS), 256>>>(Wm);
    reduce_kernel<<<(B_ * H_) / 512, 128>>>(bias, out);
}